// round 3
// baseline (speedup 1.0000x reference)
#include <cuda_runtime.h>
#include <cstdint>

// Gate_60421599920823 : MoE sigmoid gating
//   logits = x[8192,4096] @ W^T[4096,64]  (fp32)
//   scores = sigmoid(logits)
//   top-2 on (scores + bias), weights = gathered scores normalized
// Outputs (guessed concat order, selected defensively by out_size):
//   [weights (N*2) | indices-as-float (N*2) | scores (N*64)]

#define D_DIM   4096
#define NEXP    64
#define TILE_M  64
#define KC      32
#define NCHUNK  (D_DIM / KC)     // 128
#define THREADS 128
#define XPAD    36               // 144B rows: 16B-aligned, broadcast reads

typedef unsigned long long ull;

__device__ __forceinline__ void ffma2(ull& d, ull a, ull b) {
    asm("fma.rn.f32x2 %0, %1, %2, %3;" : "=l"(d) : "l"(a), "l"(b), "l"(d));
}

struct Tiles {
    float X[2][TILE_M][XPAD];    // 18432 B
    float W[2][NEXP][KC];        // 16384 B (XOR-swizzled 16B chunks)
};
struct Epi {
    float C[TILE_M][NEXP + 4];   // 17408 B
};
union SmemU { Tiles t; Epi e; };

__global__ __launch_bounds__(THREADS, 1)
void gate_kernel(const float* __restrict__ x,
                 const float* __restrict__ w,
                 const float* __restrict__ bias,
                 float* __restrict__ out_w,
                 float* __restrict__ out_i,
                 float* __restrict__ out_s)
{
    __shared__ SmemU sm;
    const int tid = threadIdx.x;
    const int tx  = tid & 7;     // expert group: experts tx + 8j, j=0..7
    const int ty  = tid >> 3;    // row group: rows ty*4 .. ty*4+3
    const int row_base = blockIdx.x * TILE_M;

    // ---- async tile loader ------------------------------------------------
    auto load_chunk = [&](int c, int buf) {
        const int k0 = c * KC;
        #pragma unroll
        for (int i = 0; i < 4; ++i) {                 // X: 64 rows x 8 float4
            int lin = tid + i * THREADS;              // 0..511
            int r   = lin >> 3;
            int c4  = lin & 7;
            const float* src = x + (size_t)(row_base + r) * D_DIM + k0 + c4 * 4;
            uint32_t dst = (uint32_t)__cvta_generic_to_shared(&sm.t.X[buf][r][c4 * 4]);
            asm volatile("cp.async.cg.shared.global [%0], [%1], 16;\n" :: "r"(dst), "l"(src));
        }
        #pragma unroll
        for (int i = 0; i < 4; ++i) {                 // W: 64 rows x 8 float4, swizzled
            int lin = tid + i * THREADS;
            int r   = lin >> 3;
            int c4  = lin & 7;
            const float* src = w + (size_t)r * D_DIM + k0 + c4 * 4;
            int sw = c4 ^ (r & 7);
            uint32_t dst = (uint32_t)__cvta_generic_to_shared(&sm.t.W[buf][r][sw * 4]);
            asm volatile("cp.async.cg.shared.global [%0], [%1], 16;\n" :: "r"(dst), "l"(src));
        }
    };

    // ---- mainloop: packed f32x2 FFMA --------------------------------------
    ull acc[4][8];
    #pragma unroll
    for (int r = 0; r < 4; ++r)
        #pragma unroll
        for (int j = 0; j < 8; ++j) acc[r][j] = 0ULL;

    load_chunk(0, 0);
    asm volatile("cp.async.commit_group;\n");

    for (int c = 0; c < NCHUNK; ++c) {
        const int cur = c & 1;
        if (c + 1 < NCHUNK) {
            load_chunk(c + 1, cur ^ 1);
            asm volatile("cp.async.commit_group;\n");
            asm volatile("cp.async.wait_group 1;\n");
        } else {
            asm volatile("cp.async.wait_group 0;\n");
        }
        __syncthreads();

        #pragma unroll
        for (int kq = 0; kq < KC; kq += 4) {
            float4 xv[4];
            #pragma unroll
            for (int r = 0; r < 4; ++r)
                xv[r] = *reinterpret_cast<const float4*>(&sm.t.X[cur][ty * 4 + r][kq]);
            float4 wv[8];
            #pragma unroll
            for (int j = 0; j < 8; ++j) {
                const int e  = tx + 8 * j;
                const int sw = (kq >> 2) ^ tx;        // (e & 7) == tx
                wv[j] = *reinterpret_cast<const float4*>(&sm.t.W[cur][e][sw * 4]);
            }
            #pragma unroll
            for (int r = 0; r < 4; ++r) {
                const ull* px = reinterpret_cast<const ull*>(&xv[r]);
                #pragma unroll
                for (int j = 0; j < 8; ++j) {
                    const ull* pw = reinterpret_cast<const ull*>(&wv[j]);
                    ffma2(acc[r][j], px[0], pw[0]);
                    ffma2(acc[r][j], px[1], pw[1]);
                }
            }
        }
        __syncthreads();   // protect buffer reuse (and smem union below)
    }

    // ---- epilogue: logits -> smem -----------------------------------------
    #pragma unroll
    for (int r = 0; r < 4; ++r)
        #pragma unroll
        for (int j = 0; j < 8; ++j) {
            float2 f = *reinterpret_cast<float2*>(&acc[r][j]);
            sm.e.C[ty * 4 + r][tx + 8 * j] = f.x + f.y;
        }
    __syncthreads();

    // sigmoid + coalesced scores store
    for (int idx = tid; idx < TILE_M * NEXP; idx += THREADS) {
        const int r = idx >> 6, e = idx & 63;
        const float v = 1.0f / (1.0f + __expf(-sm.e.C[r][e]));
        sm.e.C[r][e] = v;
        if (out_s) out_s[(size_t)(row_base + r) * NEXP + e] = v;
    }
    __syncthreads();

    // per-row top-2 (strict > keeps lowest index on ties, like lax.top_k)
    if (tid < TILE_M) {
        const int r = tid;
        float b0 = -1e30f, b1 = -1e30f;
        int   i0 = 0,      i1 = 0;
        #pragma unroll
        for (int e = 0; e < NEXP; ++e) {
            const float v = sm.e.C[r][e] + bias[e];
            if (v > b0)      { b1 = b0; i1 = i0; b0 = v; i0 = e; }
            else if (v > b1) { b1 = v;  i1 = e; }
        }
        const float w0 = sm.e.C[r][i0];
        const float w1 = sm.e.C[r][i1];
        const float inv = 1.0f / (w0 + w1);
        const int row = row_base + r;
        if (out_w) {
            out_w[row * 2 + 0] = w0 * inv;
            out_w[row * 2 + 1] = w1 * inv;
        }
        if (out_i) {
            out_i[row * 2 + 0] = (float)i0;
            out_i[row * 2 + 1] = (float)i1;
        }
    }
}

extern "C" void kernel_launch(void* const* d_in, const int* in_sizes, int n_in,
                              void* d_out, int out_size) {
    const float* x = (const float*)d_in[0];
    const float* w = (const float*)d_in[1];
    const float* b = (const float*)d_in[2];
    const int N = in_sizes[0] / D_DIM;         // 8192

    float* out = (float*)d_out;
    float* ow = nullptr; float* oi = nullptr; float* os = nullptr;
    if (out_size >= N * (2 * 2 + NEXP)) {      // full concat [w | i | s]
        ow = out; oi = out + (size_t)N * 2; os = out + (size_t)N * 4;
    } else if (out_size == N * NEXP) {         // scores only
        os = out;
    } else if (out_size == N * 4) {            // weights + indices
        ow = out; oi = out + (size_t)N * 2;
    } else {                                   // weights only
        ow = out;
    }

    gate_kernel<<<N / TILE_M, THREADS>>>(x, w, b, ow, oi, os);
}